// round 9
// baseline (speedup 1.0000x reference)
#include <cuda_runtime.h>
#include <cstdint>

// WinnerTakesAll: per-batch top-64 mask. x: (32,32,256,256) fp32.
// v9: v2's winning memory shape (512thr, 16x LDG.128 front-batched, fused
// zero-write) with all compute stripped: threshold from sampler, no smem,
// no barriers, no sorts, thread-local rare emit.

#define BATCHES 32
#define N_PER   2097152
#define N4      (N_PER / 4)

// --- sampling ---
#define TPB_S   1024
#define SAMP4   8192
#define SAMP_PER_T (SAMP4 / TPB_S)
#define SRANK   64

// --- select ---
#define TPB_A   512
#define VPT4    16
#define CHUNK4  (TPB_A * VPT4)          // 8192 float4 = 32768 elems
#define CHUNK_E (CHUNK4 * 4)
#define BPB     (N4 / CHUNK4)           // 64 blocks per batch
#define CAP     65536

// --- merge ---
#define TPB_M   512
#define NBINS   4096
#define MAXS    2048

__device__ unsigned long long g_cand[BATCHES][CAP];
__device__ int g_cnt[BATCHES];          // zero-init; merge restores to 0
__device__ int g_bin[BATCHES];

__device__ __forceinline__ unsigned key32(float v) {
    unsigned u = __float_as_uint(v);
    return (u & 0x80000000u) ? ~u : (u | 0x80000000u);
}
__device__ __forceinline__ float unkey(unsigned k) {
    return (k & 0x80000000u) ? __uint_as_float(k & 0x7fffffffu)
                             : __uint_as_float(~k);
}

// ---------------------------------------------------------------------------
// Kernel S: sampled threshold (proven ~7us). >=SRANK real elements >= bin
// floor => the true top-64 is a subset of {x >= Tf}.
// ---------------------------------------------------------------------------
__global__ void __launch_bounds__(TPB_S)
sample_kernel(const float4* __restrict__ x4) {
    __shared__ int hist[NBINS];
    __shared__ int s_wsum[TPB_S / 32];
    __shared__ int s_woff[TPB_S / 32];

    const int t = threadIdx.x, lane = t & 31, warp = t >> 5;
    const int batch = blockIdx.x;

    for (int i = t; i < NBINS; i += TPB_S) hist[i] = 0;
    __syncthreads();

    const float4* xb = x4 + (size_t)batch * N4;
    float4 v[SAMP_PER_T];
#pragma unroll
    for (int k = 0; k < SAMP_PER_T; k++)
        v[k] = xb[k * TPB_S + t];
#pragma unroll
    for (int k = 0; k < SAMP_PER_T; k++) {
        atomicAdd(&hist[key32(v[k].x) >> 20], 1);
        atomicAdd(&hist[key32(v[k].y) >> 20], 1);
        atomicAdd(&hist[key32(v[k].z) >> 20], 1);
        atomicAdd(&hist[key32(v[k].w) >> 20], 1);
    }
    __syncthreads();

    int local = 0;
#pragma unroll
    for (int i = 0; i < 4; i++) local += hist[t * 4 + i];
    int suf = local;
#pragma unroll
    for (int off = 1; off < 32; off <<= 1) {
        int o = __shfl_down_sync(0xffffffffu, suf, off);
        if (lane + off < 32) suf += o;
    }
    if (lane == 0) s_wsum[warp] = suf;
    __syncthreads();
    if (warp == 0) {
        int wv = s_wsum[lane], ws = wv;
#pragma unroll
        for (int off = 1; off < 32; off <<= 1) {
            int o = __shfl_down_sync(0xffffffffu, ws, off);
            if (lane + off < 32) ws += o;
        }
        s_woff[lane] = ws - wv;
    }
    __syncthreads();

    int suffix = suf + s_woff[warp];
    int above  = suffix - local;
    if (suffix >= SRANK && above < SRANK) {
        int c = above, b = t * 4;
        for (int bin = t * 4 + 3; bin >= t * 4; bin--) {
            c += hist[bin];
            if (c >= SRANK) { b = bin; break; }
        }
        g_bin[batch] = b;
    }
}

// ---------------------------------------------------------------------------
// Kernel A: fused streaming select. 16 front-batched LDG.128 per thread,
// 16 STG.128 zeros issued in the load-latency shadow, then register scan
// with a rarely-taken emit branch. No smem, no barriers, no ballots.
// ---------------------------------------------------------------------------
__global__ void __launch_bounds__(TPB_A)
select_kernel(const float4* __restrict__ x4, float4* __restrict__ out4) {
    const int t = threadIdx.x;
    const int batch = blockIdx.y, blk = blockIdx.x;

    const int bin = g_bin[batch];
    const float Tf = (bin < 8) ? __int_as_float(0xff800000)
                               : unkey((unsigned)bin << 20);

    const size_t base4 = (size_t)batch * N4 + (size_t)blk * CHUNK4;

    // Phase 1: all 16 loads in flight.
    float4 v[VPT4];
#pragma unroll
    for (int i = 0; i < VPT4; i++)
        v[i] = x4[base4 + i * TPB_A + t];

    // Phase 2: zero stores (independent of loads; fill the latency shadow).
    const float4 z = make_float4(0.f, 0.f, 0.f, 0.f);
#pragma unroll
    for (int i = 0; i < VPT4; i++)
        out4[base4 + i * TPB_A + t] = z;

    // Phase 3: scan registers; emit rare candidates.
    const unsigned ebase = (unsigned)(blk * CHUNK_E);
#pragma unroll
    for (int i = 0; i < VPT4; i++) {
        float m4 = fmaxf(fmaxf(v[i].x, v[i].y), fmaxf(v[i].z, v[i].w));
        if (m4 >= Tf) {                       // ~0.8% of threads per group
            unsigned e0 = ebase + (unsigned)(i * TPB_A + t) * 4u;
            float vv[4] = {v[i].x, v[i].y, v[i].z, v[i].w};
#pragma unroll
            for (int c = 0; c < 4; c++) {
                if (vv[c] >= Tf) {
                    int pos = atomicAdd(&g_cnt[batch], 1);
                    if (pos < CAP)
                        g_cand[batch][pos] =
                            ((unsigned long long)key32(vv[c]) << 32) |
                            (unsigned)(~(e0 + (unsigned)c));
                }
            }
        }
    }
}

// ---------------------------------------------------------------------------
// Kernel M: per-batch exact top-64 (proven ~11us); scatter; reset counter.
// ---------------------------------------------------------------------------
__global__ void __launch_bounds__(TPB_M)
merge_kernel(const float* __restrict__ x, float* __restrict__ out) {
    __shared__ int hist[NBINS];
    __shared__ int s_wsum[TPB_M / 32];
    __shared__ int s_woff[TPB_M / 32];
    __shared__ unsigned long long s_surv[MAXS];
    __shared__ int s_scnt;
    __shared__ unsigned s_bin;
    __shared__ int s_tot;

    const int t = threadIdx.x, lane = t & 31, warp = t >> 5;
    const int batch = blockIdx.x;
    const int raw = g_cnt[batch];
    const int cnt = min(raw, CAP);

    if (t == 0) s_scnt = 0;

    if (raw <= CAP) {
        for (int i = t; i < NBINS; i += TPB_M) hist[i] = 0;
        __syncthreads();
        for (int i = t; i < cnt; i += TPB_M)
            atomicAdd(&hist[(unsigned)(g_cand[batch][i] >> 52)], 1);
        __syncthreads();

        int local = 0;
#pragma unroll
        for (int i = 0; i < 8; i++) local += hist[t * 8 + i];
        int suf = local;
#pragma unroll
        for (int off = 1; off < 32; off <<= 1) {
            int o = __shfl_down_sync(0xffffffffu, suf, off);
            if (lane + off < 32) suf += o;
        }
        if (lane == 0) s_wsum[warp] = suf;
        __syncthreads();
        if (warp == 0 && lane < TPB_M / 32) {
            int wv = s_wsum[lane], ws = wv;
#pragma unroll
            for (int off = 1; off < TPB_M / 32; off <<= 1) {
                int o = __shfl_down_sync(0xffffu, ws, off);
                if (lane + off < TPB_M / 32) ws += o;
            }
            s_woff[lane] = ws - wv;
        }
        __syncthreads();
        int suffix = suf + s_woff[warp];
        int above  = suffix - local;
        if (suffix >= 64 && above < 64) {
            int c = above, b = t * 8;
            for (int bin = t * 8 + 7; bin >= t * 8; bin--) {
                c += hist[bin];
                if (c >= 64) { b = bin; break; }
            }
            s_bin = (unsigned)b;
        }
        __syncthreads();
        const unsigned bthr = s_bin;

        for (int i = t; i < cnt; i += TPB_M) {
            unsigned long long ck = g_cand[batch][i];
            if ((unsigned)(ck >> 52) >= bthr) {
                int p = atomicAdd(&s_scnt, 1);
                if (p < MAXS) s_surv[p] = ck;
            }
        }
        __syncthreads();
    } else {
        // Fallback (CAP overflow only): exact bitwise threshold over x.
        __syncthreads();
        const float* xb = x + (size_t)batch * N_PER;
        unsigned T = 0;
        for (int bit = 31; bit >= 0; bit--) {
            unsigned candT = T | (1u << bit);
            int c = 0;
            for (int i = t; i < N_PER; i += TPB_M) c += (key32(xb[i]) >= candT);
#pragma unroll
            for (int o = 16; o > 0; o >>= 1) c += __shfl_xor_sync(0xffffffffu, c, o);
            if (lane == 0) s_wsum[warp] = c;
            __syncthreads();
            if (t == 0) {
                int tot = 0;
                for (int w = 0; w < TPB_M / 32; w++) tot += s_wsum[w];
                s_tot = tot;
            }
            __syncthreads();
            if (s_tot >= 64) T = candT;
            __syncthreads();
        }
        for (int i = t; i < N_PER; i += TPB_M) {
            unsigned u = key32(xb[i]);
            if (u >= T) {
                int p = atomicAdd(&s_scnt, 1);
                if (p < MAXS)
                    s_surv[p] = ((unsigned long long)u << 32) | (unsigned)(~i);
            }
        }
        __syncthreads();
    }

    const int S = min(s_scnt, MAXS);
    if (t < S) {
        unsigned long long me = s_surv[t];
        int r = 0;
        for (int j = 0; j < S; j++) r += (s_surv[j] > me);
        if (r < 64) {
            unsigned idx = ~((unsigned)me);
            out[(size_t)batch * N_PER + idx] = unkey((unsigned)(me >> 32));
        }
    }
    __syncthreads();
    if (t == 0) g_cnt[batch] = 0;
}

// ---------------------------------------------------------------------------
extern "C" void kernel_launch(void* const* d_in, const int* in_sizes, int n_in,
                              void* d_out, int out_size) {
    const float* x = (const float*)d_in[0];
    float* out = (float*)d_out;

    sample_kernel<<<BATCHES, TPB_S>>>((const float4*)x);

    dim3 gA(BPB, BATCHES);
    select_kernel<<<gA, TPB_A>>>((const float4*)x, (float4*)out);

    merge_kernel<<<BATCHES, TPB_M>>>(x, out);
}

// round 10
// speedup vs baseline: 1.0408x; 1.0408x over previous
#include <cuda_runtime.h>
#include <cstdint>

// WinnerTakesAll: per-batch top-64 mask. x: (32,32,256,256) fp32.
// v10: v2's proven select skeleton (512thr, launch_bounds(512,1), VPT16,
// smem bitonic threshold) with the candidate sort removed (ballot-aggregated
// global emit) + R7's fast histogram merge. Two kernels total.

#define BATCHES 32
#define N_PER   2097152
#define N4      (N_PER / 4)

// --- select ---
#define TPB_A   512
#define VPT4    16
#define CHUNK4  (TPB_A * VPT4)          // 8192 float4 = 32768 elems
#define CHUNK_E (CHUNK4 * 4)
#define BPB     (N4 / CHUNK4)           // 64 blocks per batch
#define CAP     65536

// --- merge ---
#define TPB_M   512
#define NBINS   4096
#define MAXS    2048

__device__ unsigned long long g_cand[BATCHES][CAP];
__device__ int g_cnt[BATCHES];          // zero-init; merge restores to 0

__device__ __forceinline__ unsigned key32(float v) {
    unsigned u = __float_as_uint(v);
    return (u & 0x80000000u) ? ~u : (u | 0x80000000u);  // order-preserving
}
__device__ __forceinline__ float unkey(unsigned k) {
    return (k & 0x80000000u) ? __uint_as_float(k & 0x7fffffffu)
                             : __uint_as_float(~k);
}

// ---------------------------------------------------------------------------
// Kernel A (v2 skeleton): load chunk into regs, block threshold P via smem
// bitonic of 512 thread-maxes, ballot-aggregated candidate emit, zero-write.
// Guarantee: any batch-top-64 element has block rank <= 64, and all block
// top-64 satisfy x >= P (>=64 thread-maxes >= P), so it is emitted.
// ---------------------------------------------------------------------------
__global__ void __launch_bounds__(TPB_A, 1)
select_kernel(const float4* __restrict__ x4, float4* __restrict__ out4) {
    __shared__ float s_max[TPB_A];
    __shared__ float s_P;

    const int t = threadIdx.x;
    const int lane = t & 31;
    const int batch = blockIdx.y;
    const int blk = blockIdx.x;
    const size_t base4 = (size_t)batch * N4 + (size_t)blk * CHUNK4;

    // ---- Load 64 elements into registers; thread max ----
    float4 v[VPT4];
#pragma unroll
    for (int i = 0; i < VPT4; i++)
        v[i] = x4[base4 + (size_t)i * TPB_A + t];

    float tmax = __int_as_float(0xff800000);
#pragma unroll
    for (int i = 0; i < VPT4; i++)
        tmax = fmaxf(tmax, fmaxf(fmaxf(v[i].x, v[i].y), fmaxf(v[i].z, v[i].w)));
    s_max[t] = tmax;
    __syncthreads();

    // ---- Bitonic sort (descending) of 512 thread-maxes; P = s_max[63] ----
    for (int k = 2; k <= TPB_A; k <<= 1) {
        for (int j = k >> 1; j > 0; j >>= 1) {
            int l = t ^ j;
            if (l > t) {
                float a = s_max[t], b = s_max[l];
                bool dir = ((t & k) == 0);
                if (dir ? (a < b) : (a > b)) { s_max[t] = b; s_max[l] = a; }
            }
            __syncthreads();
        }
    }
    if (t == 0) s_P = s_max[63];
    __syncthreads();
    const float P = s_P;

    // ---- Candidate emit (ballot-aggregated global atomics) ----
    const unsigned ebase = (unsigned)(blk * CHUNK_E);
#pragma unroll
    for (int i = 0; i < VPT4; i++) {
        float vv[4] = {v[i].x, v[i].y, v[i].z, v[i].w};
#pragma unroll
        for (int c = 0; c < 4; c++) {
            bool pred = (vv[c] >= P);
            unsigned m = __ballot_sync(0xffffffffu, pred);
            if (m) {
                int leader = __ffs(m) - 1;
                int pos = 0;
                if (lane == leader)
                    pos = atomicAdd(&g_cnt[batch], __popc(m));
                pos = __shfl_sync(0xffffffffu, pos, leader);
                if (pred) {
                    int my = pos + __popc(m & ((1u << lane) - 1u));
                    if (my < CAP) {
                        unsigned e = ebase + (unsigned)(i * TPB_A + t) * 4u + (unsigned)c;
                        g_cand[batch][my] =
                            ((unsigned long long)key32(vv[c]) << 32) | (unsigned)(~e);
                    }
                }
            }
        }
    }

    // ---- Zero-write this block's output chunk ----
    const float4 z = make_float4(0.f, 0.f, 0.f, 0.f);
#pragma unroll
    for (int i = 0; i < VPT4; i++)
        out4[base4 + (size_t)i * TPB_A + t] = z;
}

// ---------------------------------------------------------------------------
// Kernel M: per-batch exact top-64 (R7-proven); scatter; reset counter.
// ---------------------------------------------------------------------------
__global__ void __launch_bounds__(TPB_M)
merge_kernel(const float* __restrict__ x, float* __restrict__ out) {
    __shared__ int hist[NBINS];
    __shared__ int s_wsum[TPB_M / 32];
    __shared__ int s_woff[TPB_M / 32];
    __shared__ unsigned long long s_surv[MAXS];
    __shared__ int s_scnt;
    __shared__ unsigned s_bin;
    __shared__ int s_tot;

    const int t = threadIdx.x, lane = t & 31, warp = t >> 5;
    const int batch = blockIdx.x;
    const int raw = g_cnt[batch];
    const int cnt = min(raw, CAP);

    if (t == 0) s_scnt = 0;

    if (raw <= CAP) {
        for (int i = t; i < NBINS; i += TPB_M) hist[i] = 0;
        __syncthreads();
        for (int i = t; i < cnt; i += TPB_M)
            atomicAdd(&hist[(unsigned)(g_cand[batch][i] >> 52)], 1);
        __syncthreads();

        int local = 0;
#pragma unroll
        for (int i = 0; i < 8; i++) local += hist[t * 8 + i];
        int suf = local;
#pragma unroll
        for (int off = 1; off < 32; off <<= 1) {
            int o = __shfl_down_sync(0xffffffffu, suf, off);
            if (lane + off < 32) suf += o;
        }
        if (lane == 0) s_wsum[warp] = suf;
        __syncthreads();
        if (warp == 0 && lane < TPB_M / 32) {
            int wv = s_wsum[lane], ws = wv;
#pragma unroll
            for (int off = 1; off < TPB_M / 32; off <<= 1) {
                int o = __shfl_down_sync(0xffffu, ws, off);
                if (lane + off < TPB_M / 32) ws += o;
            }
            s_woff[lane] = ws - wv;
        }
        __syncthreads();
        int suffix = suf + s_woff[warp];
        int above  = suffix - local;
        if (suffix >= 64 && above < 64) {
            int c = above, b = t * 8;
            for (int bin = t * 8 + 7; bin >= t * 8; bin--) {
                c += hist[bin];
                if (c >= 64) { b = bin; break; }
            }
            s_bin = (unsigned)b;
        }
        __syncthreads();
        const unsigned bthr = s_bin;

        for (int i = t; i < cnt; i += TPB_M) {
            unsigned long long ck = g_cand[batch][i];
            if ((unsigned)(ck >> 52) >= bthr) {
                int p = atomicAdd(&s_scnt, 1);
                if (p < MAXS) s_surv[p] = ck;
            }
        }
        __syncthreads();
    } else {
        // Fallback (CAP overflow only): exact bitwise threshold over x.
        __syncthreads();
        const float* xb = x + (size_t)batch * N_PER;
        unsigned T = 0;
        for (int bit = 31; bit >= 0; bit--) {
            unsigned candT = T | (1u << bit);
            int c = 0;
            for (int i = t; i < N_PER; i += TPB_M) c += (key32(xb[i]) >= candT);
#pragma unroll
            for (int o = 16; o > 0; o >>= 1) c += __shfl_xor_sync(0xffffffffu, c, o);
            if (lane == 0) s_wsum[warp] = c;
            __syncthreads();
            if (t == 0) {
                int tot = 0;
                for (int w = 0; w < TPB_M / 32; w++) tot += s_wsum[w];
                s_tot = tot;
            }
            __syncthreads();
            if (s_tot >= 64) T = candT;
            __syncthreads();
        }
        for (int i = t; i < N_PER; i += TPB_M) {
            unsigned u = key32(xb[i]);
            if (u >= T) {
                int p = atomicAdd(&s_scnt, 1);
                if (p < MAXS)
                    s_surv[p] = ((unsigned long long)u << 32) | (unsigned)(~i);
            }
        }
        __syncthreads();
    }

    const int S = min(s_scnt, MAXS);
    if (t < S) {
        unsigned long long me = s_surv[t];
        int r = 0;
        for (int j = 0; j < S; j++) r += (s_surv[j] > me);
        if (r < 64) {
            unsigned idx = ~((unsigned)me);
            out[(size_t)batch * N_PER + idx] = unkey((unsigned)(me >> 32));
        }
    }
    __syncthreads();
    if (t == 0) g_cnt[batch] = 0;
}

// ---------------------------------------------------------------------------
extern "C" void kernel_launch(void* const* d_in, const int* in_sizes, int n_in,
                              void* d_out, int out_size) {
    const float* x = (const float*)d_in[0];
    float* out = (float*)d_out;

    dim3 gA(BPB, BATCHES);
    select_kernel<<<gA, TPB_A>>>((const float4*)x, (float4*)out);

    merge_kernel<<<BATCHES, TPB_M>>>(x, out);
}

// round 11
// speedup vs baseline: 1.2307x; 1.1824x over previous
#include <cuda_runtime.h>
#include <cstdint>

// WinnerTakesAll: per-batch top-64 mask. x: (32,32,256,256) fp32.
// v11 = v2's select VERBATIM (VPT16 regs, lb(512,1), warp-shuffle bitonic ->
// 128-pool threshold, ballot emit, fused zero-write) minus its trailing
// 512-wide candidate sort (direct global emit instead) + R7 histogram merge.

#define BATCHES 32
#define N_PER   2097152
#define N4      (N_PER / 4)

// --- select ---
#define TPB_A   512
#define VPT4    16
#define CHUNK4  (TPB_A * VPT4)          // 8192 float4 = 32768 elems
#define CHUNK_E (CHUNK4 * 4)
#define BPB     (N4 / CHUNK4)           // 64 blocks per batch
#define CAP     65536

// --- merge ---
#define TPB_M   512
#define NBINS   4096
#define MAXS    2048

__device__ unsigned long long g_cand[BATCHES][CAP];
__device__ int g_cnt[BATCHES];          // zero-init; merge restores to 0

__device__ __forceinline__ unsigned key32(float v) {
    unsigned u = __float_as_uint(v);
    return (u & 0x80000000u) ? ~u : (u | 0x80000000u);  // order-preserving
}
__device__ __forceinline__ float unkey(unsigned k) {
    return (k & 0x80000000u) ? __uint_as_float(k & 0x7fffffffu)
                             : __uint_as_float(~k);
}

// ---------------------------------------------------------------------------
// Kernel A (v2 select, sort removed):
//   regs load -> thread max -> warp shuffle bitonic (desc) -> warp top-8 to
//   128-pool -> P = rank-63 of pool -> ballot-aggregated global emit ->
//   fused zero-write.
// Guarantee: >=64 thread-maxes >= P => >=64 elements >= P => block top-64
// (superset of batch winners in this chunk) all emitted.
// ---------------------------------------------------------------------------
__global__ void __launch_bounds__(TPB_A, 1)
select_kernel(const float4* __restrict__ x4, float4* __restrict__ out4) {
    __shared__ float s_pool[128];   // 16 warps x top-8 thread-maxes
    __shared__ float s_P;

    const int t = threadIdx.x;
    const int lane = t & 31;
    const int warp = t >> 5;
    const int batch = blockIdx.y;
    const int blk = blockIdx.x;
    const size_t base4 = (size_t)batch * N4 + (size_t)blk * CHUNK4;

    // ---- Load 64 elements into registers; thread max ----
    float4 v[VPT4];
#pragma unroll
    for (int i = 0; i < VPT4; i++)
        v[i] = x4[base4 + (size_t)i * TPB_A + t];

    float tmax = __int_as_float(0xff800000);
#pragma unroll
    for (int i = 0; i < VPT4; i++)
        tmax = fmaxf(tmax, fmaxf(fmaxf(v[i].x, v[i].y), fmaxf(v[i].z, v[i].w)));

    // ---- Warp-level bitonic sort (descending) of 32 thread-maxes ----
    float s = tmax;
#pragma unroll
    for (int k = 2; k <= 32; k <<= 1) {
#pragma unroll
        for (int j = k >> 1; j > 0; j >>= 1) {
            float o = __shfl_xor_sync(0xffffffffu, s, j);
            bool up = ((lane & k) == 0);
            bool lower = ((lane & j) == 0);
            s = (up == lower) ? fmaxf(s, o) : fminf(s, o);  // descending
        }
    }
    if (lane < 8) s_pool[warp * 8 + lane] = s;   // warp's top-8, desc
    __syncthreads();

    // ---- P = 64th largest of the 128-entry pool (exact rank) ----
    if (t < 128) {
        float p = s_pool[t];
        int r = 0;
#pragma unroll 8
        for (int j = 0; j < 128; j++) {
            float pj = s_pool[j];
            r += (pj > p) || (pj == p && j < t);
        }
        if (r == 63) s_P = p;
    }
    __syncthreads();
    const float P = s_P;

    // ---- Candidate emit (ballot-aggregated global atomics) ----
    const unsigned ebase = (unsigned)(blk * CHUNK_E);
#pragma unroll
    for (int i = 0; i < VPT4; i++) {
        float vv[4] = {v[i].x, v[i].y, v[i].z, v[i].w};
#pragma unroll
        for (int c = 0; c < 4; c++) {
            bool pred = (vv[c] >= P);
            unsigned m = __ballot_sync(0xffffffffu, pred);
            if (m) {
                int leader = __ffs(m) - 1;
                int pos = 0;
                if (lane == leader)
                    pos = atomicAdd(&g_cnt[batch], __popc(m));
                pos = __shfl_sync(0xffffffffu, pos, leader);
                if (pred) {
                    int my = pos + __popc(m & ((1u << lane) - 1u));
                    if (my < CAP) {
                        unsigned e = ebase + (unsigned)(i * TPB_A + t) * 4u + (unsigned)c;
                        g_cand[batch][my] =
                            ((unsigned long long)key32(vv[c]) << 32) | (unsigned)(~e);
                    }
                }
            }
        }
    }

    // ---- Zero-write this block's output chunk ----
    const float4 z = make_float4(0.f, 0.f, 0.f, 0.f);
#pragma unroll
    for (int i = 0; i < VPT4; i++)
        out4[base4 + (size_t)i * TPB_A + t] = z;
}

// ---------------------------------------------------------------------------
// Kernel M: per-batch exact top-64 (R7-proven, 9.2us); scatter; reset cnt.
// ---------------------------------------------------------------------------
__global__ void __launch_bounds__(TPB_M)
merge_kernel(const float* __restrict__ x, float* __restrict__ out) {
    __shared__ int hist[NBINS];
    __shared__ int s_wsum[TPB_M / 32];
    __shared__ int s_woff[TPB_M / 32];
    __shared__ unsigned long long s_surv[MAXS];
    __shared__ int s_scnt;
    __shared__ unsigned s_bin;
    __shared__ int s_tot;

    const int t = threadIdx.x, lane = t & 31, warp = t >> 5;
    const int batch = blockIdx.x;
    const int raw = g_cnt[batch];
    const int cnt = min(raw, CAP);

    if (t == 0) s_scnt = 0;

    if (raw <= CAP) {
        for (int i = t; i < NBINS; i += TPB_M) hist[i] = 0;
        __syncthreads();
        for (int i = t; i < cnt; i += TPB_M)
            atomicAdd(&hist[(unsigned)(g_cand[batch][i] >> 52)], 1);
        __syncthreads();

        int local = 0;
#pragma unroll
        for (int i = 0; i < 8; i++) local += hist[t * 8 + i];
        int suf = local;
#pragma unroll
        for (int off = 1; off < 32; off <<= 1) {
            int o = __shfl_down_sync(0xffffffffu, suf, off);
            if (lane + off < 32) suf += o;
        }
        if (lane == 0) s_wsum[warp] = suf;
        __syncthreads();
        if (warp == 0 && lane < TPB_M / 32) {
            int wv = s_wsum[lane], ws = wv;
#pragma unroll
            for (int off = 1; off < TPB_M / 32; off <<= 1) {
                int o = __shfl_down_sync(0xffffu, ws, off);
                if (lane + off < TPB_M / 32) ws += o;
            }
            s_woff[lane] = ws - wv;
        }
        __syncthreads();
        int suffix = suf + s_woff[warp];
        int above  = suffix - local;
        if (suffix >= 64 && above < 64) {
            int c = above, b = t * 8;
            for (int bin = t * 8 + 7; bin >= t * 8; bin--) {
                c += hist[bin];
                if (c >= 64) { b = bin; break; }
            }
            s_bin = (unsigned)b;
        }
        __syncthreads();
        const unsigned bthr = s_bin;

        for (int i = t; i < cnt; i += TPB_M) {
            unsigned long long ck = g_cand[batch][i];
            if ((unsigned)(ck >> 52) >= bthr) {
                int p = atomicAdd(&s_scnt, 1);
                if (p < MAXS) s_surv[p] = ck;
            }
        }
        __syncthreads();
    } else {
        // Fallback (CAP overflow only): exact bitwise threshold over x.
        __syncthreads();
        const float* xb = x + (size_t)batch * N_PER;
        unsigned T = 0;
        for (int bit = 31; bit >= 0; bit--) {
            unsigned candT = T | (1u << bit);
            int c = 0;
            for (int i = t; i < N_PER; i += TPB_M) c += (key32(xb[i]) >= candT);
#pragma unroll
            for (int o = 16; o > 0; o >>= 1) c += __shfl_xor_sync(0xffffffffu, c, o);
            if (lane == 0) s_wsum[warp] = c;
            __syncthreads();
            if (t == 0) {
                int tot = 0;
                for (int w = 0; w < TPB_M / 32; w++) tot += s_wsum[w];
                s_tot = tot;
            }
            __syncthreads();
            if (s_tot >= 64) T = candT;
            __syncthreads();
        }
        for (int i = t; i < N_PER; i += TPB_M) {
            unsigned u = key32(xb[i]);
            if (u >= T) {
                int p = atomicAdd(&s_scnt, 1);
                if (p < MAXS)
                    s_surv[p] = ((unsigned long long)u << 32) | (unsigned)(~i);
            }
        }
        __syncthreads();
    }

    const int S = min(s_scnt, MAXS);
    if (t < S) {
        unsigned long long me = s_surv[t];
        int r = 0;
        for (int j = 0; j < S; j++) r += (s_surv[j] > me);
        if (r < 64) {
            unsigned idx = ~((unsigned)me);
            out[(size_t)batch * N_PER + idx] = unkey((unsigned)(me >> 32));
        }
    }
    __syncthreads();
    if (t == 0) g_cnt[batch] = 0;
}

// ---------------------------------------------------------------------------
extern "C" void kernel_launch(void* const* d_in, const int* in_sizes, int n_in,
                              void* d_out, int out_size) {
    const float* x = (const float*)d_in[0];
    float* out = (float*)d_out;

    dim3 gA(BPB, BATCHES);
    select_kernel<<<gA, TPB_A>>>((const float4*)x, (float4*)out);

    merge_kernel<<<BATCHES, TPB_M>>>(x, out);
}